// round 7
// baseline (speedup 1.0000x reference)
#include <cuda_runtime.h>

#define N_NODE 100000
#define EMB    112
#define NNZ    1000000
#define BATCH  512
#define SEQL   50

#define SCAN_BLK 512
#define SCAN_NB  ((N_NODE + SCAN_BLK - 1) / SCAN_BLK)   // 196
#define NBLK_SESS 512u

// ---------------- scratch (device globals; no allocations allowed) ----------
__device__ int      g_cnt[N_NODE];            // invariant: 0 on kernel_launch entry
__device__ int      g_row_ptr[N_NODE + 1];
__device__ int      g_row_fill[N_NODE];
__device__ int      g_blocksum[SCAN_NB];
__device__ int      g_scan_done;              // invariant: 0 on entry
__device__ uint2    g_csr[NNZ];               // interleaved {val, col}
__device__ float    g_buf1[(size_t)N_NODE * EMB];
__device__ float    g_sess[BATCH * EMB];
__device__ float    g_tmp[BATCH * EMB];
__device__ float    g_accum[BATCH * EMB];
__device__ float    g_DA[BATCH * BATCH];
__device__ unsigned g_bar_arrive;             // invariant: 0 between barriers
__device__ unsigned g_bar_gen;                // monotonic across calls

// ---------------- grid-wide barrier (all 512 blocks co-resident) -------------
__device__ __forceinline__ void grid_bar() {
    __threadfence();
    __syncthreads();
    if (threadIdx.x == 0) {
        unsigned gen = atomicAdd(&g_bar_gen, 0u);
        unsigned a   = atomicAdd(&g_bar_arrive, 1u);
        if (a == NBLK_SESS - 1u) {
            atomicExch(&g_bar_arrive, 0u);
            __threadfence();
            atomicAdd(&g_bar_gen, 1u);
        } else {
            while (atomicAdd(&g_bar_gen, 0u) == gen) __nanosleep(64);
        }
    }
    __syncthreads();
}

// ---------------- count (4 edges / thread) ------------------------------------
__global__ void k_count(const int* __restrict__ rows) {
    int i = blockIdx.x * blockDim.x + threadIdx.x;
    if (i < NNZ / 4) {
        int4 r = reinterpret_cast<const int4*>(rows)[i];
        atomicAdd(&g_cnt[r.x], 1);
        atomicAdd(&g_cnt[r.y], 1);
        atomicAdd(&g_cnt[r.z], 1);
        atomicAdd(&g_cnt[r.w], 1);
    }
}

// ---------------- scan1 + scan2 fused (last block scans block sums) -----------
__global__ void k_scan12() {
    __shared__ int ws[SCAN_BLK / 32];
    __shared__ int s_last;
    const int tid  = threadIdx.x;
    const int lane = tid & 31;
    const int wid  = tid >> 5;
    const int i    = blockIdx.x * SCAN_BLK + tid;

    int v = (i < N_NODE) ? g_cnt[i] : 0;
    if (i < N_NODE) g_cnt[i] = 0;             // reset invariant for next call

    int inc = v;
    #pragma unroll
    for (int off = 1; off < 32; off <<= 1) {
        int t = __shfl_up_sync(0xffffffffu, inc, off);
        if (lane >= off) inc += t;
    }
    if (lane == 31) ws[wid] = inc;
    __syncthreads();
    if (wid == 0) {
        int s = (lane < SCAN_BLK / 32) ? ws[lane] : 0;
        #pragma unroll
        for (int off = 1; off < SCAN_BLK / 32; off <<= 1) {
            int t = __shfl_up_sync(0xffffffffu, s, off);
            if (lane >= off) s += t;
        }
        if (lane < SCAN_BLK / 32) ws[lane] = s;
    }
    __syncthreads();

    int excl = inc - v + (wid > 0 ? ws[wid - 1] : 0);
    if (i < N_NODE) g_row_ptr[i] = excl;
    if (tid == SCAN_BLK - 1) {
        g_blocksum[blockIdx.x] = excl + v;
        __threadfence();
    }
    __syncthreads();

    if (tid == 0) {
        int t = atomicAdd(&g_scan_done, 1);
        s_last = (t == SCAN_NB - 1);
        if (s_last) g_scan_done = 0;           // reset invariant
    }
    __syncthreads();
    if (!s_last) return;

    // last block: exclusive scan of SCAN_NB block sums with SCAN_BLK threads
    __syncthreads();
    int v2 = (tid < SCAN_NB) ? g_blocksum[tid] : 0;
    int inc2 = v2;
    #pragma unroll
    for (int off = 1; off < 32; off <<= 1) {
        int t = __shfl_up_sync(0xffffffffu, inc2, off);
        if (lane >= off) inc2 += t;
    }
    if (lane == 31) ws[wid] = inc2;
    __syncthreads();
    if (wid == 0) {
        int s = (lane < SCAN_BLK / 32) ? ws[lane] : 0;
        #pragma unroll
        for (int off = 1; off < SCAN_BLK / 32; off <<= 1) {
            int t = __shfl_up_sync(0xffffffffu, s, off);
            if (lane >= off) s += t;
        }
        if (lane < SCAN_BLK / 32) ws[lane] = s;
    }
    __syncthreads();
    int excl2 = inc2 - v2 + (wid > 0 ? ws[wid - 1] : 0);
    if (tid < SCAN_NB) g_blocksum[tid] = excl2;
    if (tid == SCAN_NB - 1) g_row_ptr[N_NODE] = excl2 + v2;
}

// ---------------- scan3: propagate block offsets -------------------------------
__global__ void k_scan3() {
    int i = blockIdx.x * blockDim.x + threadIdx.x;
    if (i < N_NODE) {
        int p = g_row_ptr[i] + g_blocksum[i / SCAN_BLK];
        g_row_ptr[i]  = p;
        g_row_fill[i] = p;
    }
}

// ---------------- scatter (4 edges / thread) ------------------------------------
__global__ void k_scatter(const float* __restrict__ vals,
                          const int* __restrict__ rows,
                          const int* __restrict__ cols) {
    int i = blockIdx.x * blockDim.x + threadIdx.x;
    if (i < NNZ / 4) {
        int4   r = reinterpret_cast<const int4*>(rows)[i];
        int4   c = reinterpret_cast<const int4*>(cols)[i];
        float4 v = reinterpret_cast<const float4*>(vals)[i];
        int p;
        p = atomicAdd(&g_row_fill[r.x], 1); g_csr[p] = make_uint2(__float_as_uint(v.x), (unsigned)c.x);
        p = atomicAdd(&g_row_fill[r.y], 1); g_csr[p] = make_uint2(__float_as_uint(v.y), (unsigned)c.y);
        p = atomicAdd(&g_row_fill[r.z], 1); g_csr[p] = make_uint2(__float_as_uint(v.z), (unsigned)c.z);
        p = atomicAdd(&g_row_fill[r.w], 1); g_csr[p] = make_uint2(__float_as_uint(v.w), (unsigned)c.w);
    }
}

// ---------------- gather core: acc += sum over edges val * x[col] --------------
__device__ __forceinline__ void row_gather(int s, int e, const float* __restrict__ x,
                                           int lane, bool act, float4& acc) {
    int k = s;
    for (; k + 3 < e; k += 4) {
        uint2 m0 = g_csr[k];
        uint2 m1 = g_csr[k + 1];
        uint2 m2 = g_csr[k + 2];
        uint2 m3 = g_csr[k + 3];
        if (act) {
            float4 a = *reinterpret_cast<const float4*>(x + (size_t)m0.y * EMB + lane * 4);
            float4 b = *reinterpret_cast<const float4*>(x + (size_t)m1.y * EMB + lane * 4);
            float4 c = *reinterpret_cast<const float4*>(x + (size_t)m2.y * EMB + lane * 4);
            float4 d = *reinterpret_cast<const float4*>(x + (size_t)m3.y * EMB + lane * 4);
            float v0 = __uint_as_float(m0.x), v1 = __uint_as_float(m1.x);
            float v2 = __uint_as_float(m2.x), v3 = __uint_as_float(m3.x);
            acc.x += v0 * a.x + v1 * b.x + v2 * c.x + v3 * d.x;
            acc.y += v0 * a.y + v1 * b.y + v2 * c.y + v3 * d.y;
            acc.z += v0 * a.z + v1 * b.z + v2 * c.z + v3 * d.z;
            acc.w += v0 * a.w + v1 * b.w + v2 * c.w + v3 * d.w;
        }
    }
    for (; k < e; k++) {
        uint2 m = g_csr[k];
        if (act) {
            float4 a = *reinterpret_cast<const float4*>(x + (size_t)m.y * EMB + lane * 4);
            float v = __uint_as_float(m.x);
            acc.x += v * a.x; acc.y += v * a.y; acc.z += v * a.z; acc.w += v * a.w;
        }
    }
}

// ---------------- SpMM pass 1: buf1 = A @ emb (all rows) ------------------------
__global__ void k_spmm1(const float* __restrict__ emb) {
    int warp = (blockIdx.x * blockDim.x + threadIdx.x) >> 5;
    int lane = threadIdx.x & 31;
    if (warp >= N_NODE) return;
    bool act = lane < (EMB / 4);
    float4 acc = make_float4(0.f, 0.f, 0.f, 0.f);
    row_gather(g_row_ptr[warp], g_row_ptr[warp + 1], emb, lane, act, acc);
    if (act)
        *reinterpret_cast<float4*>(g_buf1 + (size_t)warp * EMB + lane * 4) = acc;
}

// ---------------- fused sessconv: pool(+spmm2), DA, 2x(linear,danorm) ----------
__global__ void __launch_bounds__(128, 8) k_sess(
    const float* __restrict__ emb, const int* __restrict__ items,
    const float* __restrict__ slen, const float* __restrict__ D,
    const float* __restrict__ A, const float* __restrict__ wsess,
    float* __restrict__ out)
{
    __shared__ float smem[2112];                 // 8448 B, reused per phase
    const int tid  = threadIdx.x;
    const int lane = tid & 31;
    const int w    = tid >> 5;                    // warp 0..3
    const int b    = blockIdx.x;

    // ---- phase 0: pool with on-the-fly layer-2 rows -------------------------
    {
        bool act = lane < (EMB / 4);
        float4 acc = make_float4(0.f, 0.f, 0.f, 0.f);
        for (int l = w; l < SEQL; l += 4) {
            int it = items[b * SEQL + l];
            if (it > 0) {
                int row = it - 1;
                if (act) {
                    float4 ev = *reinterpret_cast<const float4*>(emb    + (size_t)row * EMB + lane * 4);
                    float4 bv = *reinterpret_cast<const float4*>(g_buf1 + (size_t)row * EMB + lane * 4);
                    acc.x += ev.x + bv.x; acc.y += ev.y + bv.y;
                    acc.z += ev.z + bv.z; acc.w += ev.w + bv.w;
                }
                row_gather(g_row_ptr[row], g_row_ptr[row + 1], g_buf1, lane, act, acc);
            }
        }
        float4* red4 = reinterpret_cast<float4*>(smem);   // [4][28]
        if (act) red4[w * 28 + lane] = acc;
        __syncthreads();
        if (w == 0 && act) {
            float4 t0 = red4[lane], t1 = red4[28 + lane];
            float4 t2 = red4[56 + lane], t3 = red4[84 + lane];
            float sc = (1.0f / 3.0f) / slen[b];
            float4 t;
            t.x = (t0.x + t1.x + t2.x + t3.x) * sc;
            t.y = (t0.y + t1.y + t2.y + t3.y) * sc;
            t.z = (t0.z + t1.z + t2.z + t3.z) * sc;
            t.w = (t0.w + t1.w + t2.w + t3.w) * sc;
            reinterpret_cast<float4*>(g_sess  + b * EMB)[lane] = t;
            reinterpret_cast<float4*>(g_accum + b * EMB)[lane] = t;
        }
    }
    grid_bar();

    // ---- phase 1: DA = D @ A (blocks 0..255, 32x32 tiles) --------------------
    if (b < 256) {
        float* sD = smem;                        // [32][33]
        float* sA = smem + 32 * 33;              // [32][33]
        const int bx = b & 15, by = b >> 4;
        const int tx = tid & 31, ty = tid >> 5;  // ty 0..3
        float acc8[8] = {0.f, 0.f, 0.f, 0.f, 0.f, 0.f, 0.f, 0.f};
        for (int k0 = 0; k0 < 512; k0 += 32) {
            #pragma unroll
            for (int r = 0; r < 8; r++) {
                int rr = ty + r * 4;
                sD[rr * 33 + tx] = D[(by * 32 + rr) * 512 + k0 + tx];
                sA[rr * 33 + tx] = A[(k0 + rr) * 512 + bx * 32 + tx];
            }
            __syncthreads();
            #pragma unroll
            for (int kk = 0; kk < 32; kk++) {
                float a = sA[kk * 33 + tx];
                #pragma unroll
                for (int r = 0; r < 8; r++)
                    acc8[r] += sD[(ty + r * 4) * 33 + kk] * a;
            }
            __syncthreads();
        }
        #pragma unroll
        for (int r = 0; r < 8; r++)
            g_DA[(by * 32 + ty + r * 4) * 512 + bx * 32 + tx] = acc8[r];
    }
    grid_bar();

    // ---- phases 2..5: (linear -> danorm) x 2 ---------------------------------
    #pragma unroll 1
    for (int layer = 0; layer < 2; layer++) {
        // linear: tmp[b] = sess[b] @ W^T  (all 512 blocks)
        {
            const float* wl = wsess + layer * EMB * EMB;
            if (tid < EMB) smem[tid] = g_sess[b * EMB + tid];
            __syncthreads();
            if (tid < EMB) {
                float accL = 0.f;
                #pragma unroll 8
                for (int k = 0; k < EMB; k++) accL += smem[k] * wl[tid * EMB + k];
                g_tmp[b * EMB + tid] = accL;
            }
        }
        grid_bar();

        // danorm: blocks 0..127 handle 4 batch rows each
        if (b < 128) {
            float a4[4] = {0.f, 0.f, 0.f, 0.f};
            const int c  = tid;                   // 0..127, active < 112
            const int r0 = b * 4;
            if (c < EMB) {
                for (int j = 0; j < 512; j++) {
                    float t = g_tmp[j * EMB + c];
                    a4[0] += g_DA[(r0 + 0) * 512 + j] * t;
                    a4[1] += g_DA[(r0 + 1) * 512 + j] * t;
                    a4[2] += g_DA[(r0 + 2) * 512 + j] * t;
                    a4[3] += g_DA[(r0 + 3) * 512 + j] * t;
                }
            }
            float* red = smem;                    // [4][128]
            #pragma unroll
            for (int r = 0; r < 4; r++)
                red[r * 128 + tid] = (c < EMB) ? a4[r] * a4[r] : 0.f;
            __syncthreads();
            for (int off = 64; off > 0; off >>= 1) {
                if (tid < off) {
                    #pragma unroll
                    for (int r = 0; r < 4; r++)
                        red[r * 128 + tid] += red[r * 128 + tid + off];
                }
                __syncthreads();
            }
            if (c < EMB) {
                #pragma unroll
                for (int r = 0; r < 4; r++) {
                    float inv = 1.0f / fmaxf(sqrtf(red[r * 128]), 1e-12f);
                    float v = a4[r] * inv;
                    int idx = (r0 + r) * EMB + c;
                    if (layer == 1) {
                        out[idx] = (g_accum[idx] + v) * (1.0f / 3.0f);
                    } else {
                        g_sess[idx]   = v;
                        g_accum[idx] += v;
                    }
                }
            }
        }
        grid_bar();
    }
}

// ---------------- launch ----------------------------------------------------------
extern "C" void kernel_launch(void* const* d_in, const int* in_sizes, int n_in,
                              void* d_out, int out_size) {
    const float* emb   = (const float*)d_in[0];
    const float* vals  = (const float*)d_in[1];
    const int*   rows  = (const int*)d_in[2];
    const int*   cols  = (const int*)d_in[3];
    const float* D     = (const float*)d_in[4];
    const float* A     = (const float*)d_in[5];
    const int*   items = (const int*)d_in[6];
    const float* slen  = (const float*)d_in[7];
    const float* wsess = (const float*)d_in[8];
    float* out = (float*)d_out;

    (void)in_sizes; (void)n_in; (void)out_size;

    k_count  <<<(NNZ / 4 + 255) / 256, 256>>>(rows);
    k_scan12 <<<SCAN_NB, SCAN_BLK>>>();
    k_scan3  <<<(N_NODE + 255) / 256, 256>>>();
    k_scatter<<<(NNZ / 4 + 255) / 256, 256>>>(vals, rows, cols);
    k_spmm1  <<<(N_NODE * 32 + 255) / 256, 256>>>(emb);
    k_sess   <<<NBLK_SESS, 128>>>(emb, items, slen, D, A, wsess, out);
}